// round 9
// baseline (speedup 1.0000x reference)
#include <cuda_runtime.h>
#include <cuda_bf16.h>
#include <cstdint>
#include <cstddef>

#define RTOT 32768
#define CINK 512
#define ETOT 640
#define ENT  320
#define DD   256

// ---------------- device scratch ----------------
__device__ __nv_bfloat16 g_xhi[(size_t)RTOT * CINK];
__device__ __nv_bfloat16 g_xlo[(size_t)RTOT * CINK];
__device__ __nv_bfloat16 g_p_hi[(size_t)RTOT * ETOT];
__device__ __nv_bfloat16 g_p_lo[(size_t)RTOT * ETOT];
__device__ float         g_Z[RTOT];
__device__ __nv_bfloat16 g_Whi[ETOT * CINK];
__device__ __nv_bfloat16 g_Wlo[ETOT * CINK];
__device__ __nv_bfloat16 g_CBThi[2 * DD * ENT];
__device__ __nv_bfloat16 g_CBTlo[2 * DD * ENT];

// ---------------- helpers ----------------
__device__ __forceinline__ uint32_t smem_u32(const void* p) {
    uint32_t a;
    asm("{ .reg .u64 t; cvta.to.shared.u64 t, %1; cvt.u32.u64 %0, t; }" : "=r"(a) : "l"(p));
    return a;
}
#define SWZ(o) ((uint32_t)(o) ^ ((((uint32_t)(o)) >> 3) & 0x70))

#define LDMX4(d, addr) \
    asm volatile("ldmatrix.sync.aligned.m8n8.x4.shared.b16 {%0,%1,%2,%3}, [%4];" \
                 : "=r"((d)[0]), "=r"((d)[1]), "=r"((d)[2]), "=r"((d)[3]) : "r"(addr))

#define MMA16(c, a, b0, b1) \
    asm volatile("mma.sync.aligned.m16n8k16.row.col.f32.bf16.bf16.f32 " \
                 "{%0,%1,%2,%3},{%4,%5,%6,%7},{%8,%9},{%0,%1,%2,%3};" \
                 : "+f"((c)[0]), "+f"((c)[1]), "+f"((c)[2]), "+f"((c)[3]) \
                 : "r"((a)[0]), "r"((a)[1]), "r"((a)[2]), "r"((a)[3]), "r"(b0), "r"(b1))

#define CP16(saddr, gptr) \
    asm volatile("cp.async.cg.shared.global [%0], [%1], 16;" :: "r"(saddr), "l"(gptr) : "memory")
#define CP_COMMIT() asm volatile("cp.async.commit_group;" ::: "memory")
#define CP_WAIT2()  asm volatile("cp.async.wait_group 2;" ::: "memory")

__device__ __forceinline__ void split1(float v, uint32_t& h, uint32_t& l) {
    __nv_bfloat16 hb = __float2bfloat16(v);
    h = __bfloat16_as_ushort(hb);
    l = __bfloat16_as_ushort(__float2bfloat16(v - __bfloat162float(hb)));
}

// Stage = 32KB: A tile [128r x (32 hi | 32 lo) cols] = 16KB at +0, B tile same at +16384.
#define STG 32768
static constexpr int SMEM_BYTES = 3 * STG;   // 96KB/CTA -> 2 CTAs/SM

// ---- 3-split MMA over one 128x128x32 chunk; 8 warps, warp tile 32x64 ----
// MMA order per B-fragment: 4x hh, 4x hl, 4x lh -> dependent distance 4 (covers HMMA latency)
__device__ __forceinline__ void compute_chunk(uint32_t base, float acc[2][8][4],
                                              int lane, int wm, int wn)
{
    const uint32_t saA = base, saB = base + 16384;
    #pragma unroll
    for (int ks = 0; ks < 2; ks++) {
        uint32_t ah[2][4], al[2][4];
        const uint32_t kb = ks * 32 + (lane >> 4) * 16;
        #pragma unroll
        for (int mf = 0; mf < 2; mf++) {
            uint32_t rb = (wm * 32 + mf * 16 + (lane & 15)) * 128;
            LDMX4(ah[mf], saA + SWZ(rb + kb));
            LDMX4(al[mf], saA + SWZ(rb + 64 + kb));
        }
        const uint32_t kbB = ks * 32 + ((lane >> 3) & 1) * 16;
        #pragma unroll
        for (int np = 0; np < 4; np++) {
            uint32_t rb = (wn * 64 + np * 16 + ((lane >> 4) << 3) + (lane & 7)) * 128;
            uint32_t bh[4], bl[4];
            LDMX4(bh, saB + SWZ(rb + kbB));
            LDMX4(bl, saB + SWZ(rb + 64 + kbB));
            // hh block: 4 independent MMAs
            MMA16(acc[0][2 * np],     ah[0], bh[0], bh[1]);
            MMA16(acc[0][2 * np + 1], ah[0], bh[2], bh[3]);
            MMA16(acc[1][2 * np],     ah[1], bh[0], bh[1]);
            MMA16(acc[1][2 * np + 1], ah[1], bh[2], bh[3]);
            // hl block
            MMA16(acc[0][2 * np],     ah[0], bl[0], bl[1]);
            MMA16(acc[0][2 * np + 1], ah[0], bl[2], bl[3]);
            MMA16(acc[1][2 * np],     ah[1], bl[0], bl[1]);
            MMA16(acc[1][2 * np + 1], ah[1], bl[2], bl[3]);
            // lh block
            MMA16(acc[0][2 * np],     al[0], bh[0], bh[1]);
            MMA16(acc[0][2 * np + 1], al[0], bh[2], bh[3]);
            MMA16(acc[1][2 * np],     al[1], bh[0], bh[1]);
            MMA16(acc[1][2 * np + 1], al[1], bh[2], bh[3]);
        }
    }
}

// Generic stage loader (256 threads): 32 K-cols from k0, hi|lo packed per 128B row.
__device__ __forceinline__ void load_stage(uint32_t base, int tid,
    const __nv_bfloat16* __restrict__ ahi, const __nv_bfloat16* __restrict__ alo,
    size_t aoff, int astr,
    const __nv_bfloat16* __restrict__ bhi, const __nv_bfloat16* __restrict__ blo,
    size_t boff, int bstr, int k0)
{
    #pragma unroll
    for (int j = 0; j < 4; j++) {
        int i = tid + j * 256;
        int r = i >> 3, c = i & 7;
        int hi = (c < 4), cc = c & 3;
        uint32_t dst = SWZ(r * 128 + (hi ? 0 : 64) + cc * 16);
        const __nv_bfloat16* asrc = (hi ? ahi : alo) + aoff + (size_t)r * astr + k0 + cc * 8;
        const __nv_bfloat16* bsrc = (hi ? bhi : blo) + boff + (size_t)r * bstr + k0 + cc * 8;
        CP16(base + dst,         asrc);
        CP16(base + 16384 + dst, bsrc);
    }
}

// ---------------- prep kernels ----------------
__global__ void split_x(const float* __restrict__ x) {
    size_t i = (size_t)blockIdx.x * 256 + threadIdx.x;
    float4 v = __ldg((const float4*)x + i);
    uint32_t h0, l0, h1, l1, h2, l2, h3, l3;
    split1(v.x, h0, l0); split1(v.y, h1, l1); split1(v.z, h2, l2); split1(v.w, h3, l3);
    *(uint2*)(g_xhi + i * 4) = make_uint2(h0 | (h1 << 16), h2 | (h3 << 16));
    *(uint2*)(g_xlo + i * 4) = make_uint2(l0 | (l1 << 16), l2 | (l3 << 16));
}
__global__ void split_w(const float* __restrict__ Wp) {
    int i = blockIdx.x * 256 + threadIdx.x;
    if (i < ETOT * CINK) {
        uint32_t h, l; split1(__ldg(Wp + i), h, l);
        g_Whi[i] = __ushort_as_bfloat16((unsigned short)h);
        g_Wlo[i] = __ushort_as_bfloat16((unsigned short)l);
    }
}
__global__ void split_cbt(const float* __restrict__ cb) {
    int i = blockIdx.x * 256 + threadIdx.x;   // i = (g*DD + d)*ENT + e
    if (i < 2 * DD * ENT) {
        int e = i % ENT, d = (i / ENT) % DD, g = i / (ENT * DD);
        uint32_t h, l; split1(__ldg(cb + ((size_t)g * ENT + e) * DD + d), h, l);
        g_CBThi[i] = __ushort_as_bfloat16((unsigned short)h);
        g_CBTlo[i] = __ushort_as_bfloat16((unsigned short)l);
    }
}

// ---------------- kernel 1: logits GEMM + fused exp(logit+bias+gumbel) ----------------
__global__ __launch_bounds__(256, 2) void gemm1(
    const float* __restrict__ bp, const float* __restrict__ gum)
{
    extern __shared__ char smem[];
    const uint32_t sb = smem_u32(smem);
    const int tid = threadIdx.x, lane = tid & 31, wid = tid >> 5;
    const int wm = wid & 3, wn = wid >> 2;
    const int row0 = blockIdx.x * 128, bn0 = blockIdx.y * 128;

    float acc[2][8][4];
    #pragma unroll
    for (int i = 0; i < 2; i++)
        #pragma unroll
        for (int j = 0; j < 8; j++)
            #pragma unroll
            for (int q = 0; q < 4; q++) acc[i][j][q] = 0.f;

    load_stage(sb,       tid, g_xhi, g_xlo, (size_t)row0 * CINK, CINK,
               g_Whi, g_Wlo, (size_t)bn0 * CINK, CINK, 0);  CP_COMMIT();
    load_stage(sb + STG, tid, g_xhi, g_xlo, (size_t)row0 * CINK, CINK,
               g_Whi, g_Wlo, (size_t)bn0 * CINK, CINK, 32); CP_COMMIT();

    for (int kc = 0; kc < 16; kc++) {
        if (kc + 2 < 16)
            load_stage(sb + ((kc + 2) % 3) * STG, tid, g_xhi, g_xlo, (size_t)row0 * CINK, CINK,
                       g_Whi, g_Wlo, (size_t)bn0 * CINK, CINK, (kc + 2) * 32);
        CP_COMMIT();
        CP_WAIT2();
        __syncthreads();
        compute_chunk(sb + (kc % 3) * STG, acc, lane, wm, wn);
        __syncthreads();
    }

    // epilogue: p = exp(logit + bias + gumbel), store bf16 hi/lo
    #pragma unroll
    for (int mf = 0; mf < 2; mf++) {
        #pragma unroll
        for (int h = 0; h < 2; h++) {
            const int r = wm * 32 + mf * 16 + (lane >> 2) + h * 8;
            const size_t grow = row0 + r;
            #pragma unroll
            for (int nf = 0; nf < 8; nf++) {
                const int e = bn0 + wn * 64 + nf * 8 + (lane & 3) * 2;
                float2 gv = *(const float2*)(gum + grow * ETOT + e);
                float2 bv = *(const float2*)(bp + e);
                float p0 = __expf(acc[mf][nf][h * 2 + 0] + bv.x + gv.x);
                float p1 = __expf(acc[mf][nf][h * 2 + 1] + bv.y + gv.y);
                uint32_t h0, l0, h1, l1;
                split1(p0, h0, l0); split1(p1, h1, l1);
                *(uint32_t*)(g_p_hi + grow * ETOT + e) = h0 | (h1 << 16);
                *(uint32_t*)(g_p_lo + grow * ETOT + e) = l0 | (l1 << 16);
            }
        }
    }
}

// ---------------- Z kernel: deterministic per-row sum of p ----------------
__global__ __launch_bounds__(256) void zsum() {
    const int r = blockIdx.x * 8 + (threadIdx.x >> 5);
    const int lane = threadIdx.x & 31;
    const uint32_t* ph = (const uint32_t*)(g_p_hi + (size_t)r * ETOT);
    const uint32_t* pl = (const uint32_t*)(g_p_lo + (size_t)r * ETOT);
    float s = 0.f;
    #pragma unroll
    for (int i = lane; i < ETOT / 2; i += 32) {
        uint32_t hw = __ldg(ph + i), lw = __ldg(pl + i);
        float2 hf = __bfloat1622float2(*(const __nv_bfloat162*)&hw);
        float2 lf = __bfloat1622float2(*(const __nv_bfloat162*)&lw);
        s += (hf.x + lf.x) + (hf.y + lf.y);
    }
    #pragma unroll
    for (int o = 16; o; o >>= 1) s += __shfl_xor_sync(0xFFFFFFFFu, s, o);
    if (lane == 0) g_Z[r] = s;
}

// ---------------- kernel 2: block-diagonal codebook GEMM, /Z epilogue ----------------
__global__ __launch_bounds__(256, 2) void gemm2(float* __restrict__ out)
{
    extern __shared__ char smem[];
    const uint32_t sb = smem_u32(smem);
    const int tid = threadIdx.x, lane = tid & 31, wid = tid >> 5;
    const int wm = wid & 3, wn = wid >> 2;
    const int row0 = blockIdx.x * 128;
    const int g = blockIdx.y >> 1;
    const int d0 = (blockIdx.y & 1) * 128;
    const int oc0 = blockIdx.y * 128;

    float acc[2][8][4];
    #pragma unroll
    for (int i = 0; i < 2; i++)
        #pragma unroll
        for (int j = 0; j < 8; j++)
            #pragma unroll
            for (int q = 0; q < 4; q++) acc[i][j][q] = 0.f;

    const size_t aoff = (size_t)row0 * ETOT + (size_t)g * ENT;
    const size_t boff = (size_t)(g * DD + d0) * ENT;

    load_stage(sb,       tid, g_p_hi, g_p_lo, aoff, ETOT, g_CBThi, g_CBTlo, boff, ENT, 0);  CP_COMMIT();
    load_stage(sb + STG, tid, g_p_hi, g_p_lo, aoff, ETOT, g_CBThi, g_CBTlo, boff, ENT, 32); CP_COMMIT();

    for (int kc = 0; kc < 10; kc++) {
        if (kc + 2 < 10)
            load_stage(sb + ((kc + 2) % 3) * STG, tid, g_p_hi, g_p_lo, aoff, ETOT,
                       g_CBThi, g_CBTlo, boff, ENT, (kc + 2) * 32);
        CP_COMMIT();
        CP_WAIT2();
        __syncthreads();
        compute_chunk(sb + (kc % 3) * STG, acc, lane, wm, wn);
        __syncthreads();
    }

    // epilogue: out = acc / Z
    #pragma unroll
    for (int mf = 0; mf < 2; mf++) {
        #pragma unroll
        for (int h = 0; h < 2; h++) {
            const int r = wm * 32 + mf * 16 + (lane >> 2) + h * 8;
            const size_t grow = row0 + r;
            const float rz = 1.0f / g_Z[grow];
            #pragma unroll
            for (int nf = 0; nf < 8; nf++) {
                const int oc = oc0 + wn * 64 + nf * 8 + (lane & 3) * 2;
                float2 o;
                o.x = acc[mf][nf][h * 2 + 0] * rz;
                o.y = acc[mf][nf][h * 2 + 1] * rz;
                *(float2*)(out + grow * 512 + oc) = o;
            }
        }
    }
}

// ---------------- launch ----------------
extern "C" void kernel_launch(void* const* d_in, const int* in_sizes, int n_in,
                              void* d_out, int out_size) {
    const float* x  = (const float*)d_in[0];
    const float* Wp = (const float*)d_in[1];
    const float* bp = (const float*)d_in[2];
    const float* cb = (const float*)d_in[3];
    const float* gu = (const float*)d_in[4];
    float* out = (float*)d_out;

    cudaFuncSetAttribute(gemm1, cudaFuncAttributeMaxDynamicSharedMemorySize, SMEM_BYTES);
    cudaFuncSetAttribute(gemm2, cudaFuncAttributeMaxDynamicSharedMemorySize, SMEM_BYTES);

    split_x<<<(RTOT * CINK / 4) / 256, 256>>>(x);
    split_w<<<(ETOT * CINK + 255) / 256, 256>>>(Wp);
    split_cbt<<<(2 * DD * ENT + 255) / 256, 256>>>(cb);
    gemm1<<<dim3(RTOT / 128, ETOT / 128), 256, SMEM_BYTES>>>(bp, gu);
    zsum<<<RTOT / 8, 256>>>();
    gemm2<<<dim3(RTOT / 128, 4), 256, SMEM_BYTES>>>(out);
}

// round 10
// speedup vs baseline: 1.2678x; 1.2678x over previous
#include <cuda_runtime.h>
#include <cuda_bf16.h>
#include <cuda_fp16.h>
#include <cstdint>
#include <cstddef>

#define RTOT 32768
#define CINK 512
#define ETOT 640
#define ENT  320
#define DD   256

// ---------------- device scratch ----------------
__device__ __half         g_xh16[(size_t)RTOT * CINK];
__device__ __half         g_xl16[(size_t)RTOT * CINK];
__device__ __half         g_W16[ETOT * CINK];
__device__ __nv_bfloat16 g_p_hi[(size_t)RTOT * ETOT];
__device__ __nv_bfloat16 g_p_lo[(size_t)RTOT * ETOT];
__device__ float         g_Z[RTOT];
__device__ __nv_bfloat16 g_CBThi[2 * DD * ENT];
__device__ __nv_bfloat16 g_CBTlo[2 * DD * ENT];

// ---------------- helpers ----------------
__device__ __forceinline__ uint32_t smem_u32(const void* p) {
    uint32_t a;
    asm("{ .reg .u64 t; cvta.to.shared.u64 t, %1; cvt.u32.u64 %0, t; }" : "=r"(a) : "l"(p));
    return a;
}
#define SWZ(o)   ((uint32_t)(o) ^ ((((uint32_t)(o)) >> 3) & 0x70))
#define SWZ64(o) ((uint32_t)(o) ^ ((((uint32_t)(o)) >> 3) & 0x30))

#define LDMX4(d, addr) \
    asm volatile("ldmatrix.sync.aligned.m8n8.x4.shared.b16 {%0,%1,%2,%3}, [%4];" \
                 : "=r"((d)[0]), "=r"((d)[1]), "=r"((d)[2]), "=r"((d)[3]) : "r"(addr))

#define MMAB16(c, a, b0, b1) \
    asm volatile("mma.sync.aligned.m16n8k16.row.col.f32.bf16.bf16.f32 " \
                 "{%0,%1,%2,%3},{%4,%5,%6,%7},{%8,%9},{%0,%1,%2,%3};" \
                 : "+f"((c)[0]), "+f"((c)[1]), "+f"((c)[2]), "+f"((c)[3]) \
                 : "r"((a)[0]), "r"((a)[1]), "r"((a)[2]), "r"((a)[3]), "r"(b0), "r"(b1))

#define MMAF16(c, a, b0, b1) \
    asm volatile("mma.sync.aligned.m16n8k16.row.col.f32.f16.f16.f32 " \
                 "{%0,%1,%2,%3},{%4,%5,%6,%7},{%8,%9},{%0,%1,%2,%3};" \
                 : "+f"((c)[0]), "+f"((c)[1]), "+f"((c)[2]), "+f"((c)[3]) \
                 : "r"((a)[0]), "r"((a)[1]), "r"((a)[2]), "r"((a)[3]), "r"(b0), "r"(b1))

#define CP16(saddr, gptr) \
    asm volatile("cp.async.cg.shared.global [%0], [%1], 16;" :: "r"(saddr), "l"(gptr) : "memory")
#define CP_COMMIT() asm volatile("cp.async.commit_group;" ::: "memory")
#define CP_WAIT2()  asm volatile("cp.async.wait_group 2;" ::: "memory")

__device__ __forceinline__ void split1(float v, uint32_t& h, uint32_t& l) {
    __nv_bfloat16 hb = __float2bfloat16(v);
    h = __bfloat16_as_ushort(hb);
    l = __bfloat16_as_ushort(__float2bfloat16(v - __bfloat162float(hb)));
}
__device__ __forceinline__ void split1h(float v, uint32_t& h, uint32_t& l) {
    __half hb = __float2half(v);
    h = __half_as_ushort(hb);
    l = __half_as_ushort(__float2half(v - __half2float(hb)));
}

// gemm1 stage: A [128r x (32 hi | 32 lo) fp16] = 16KB (128B rows, SW128);
//              B [128r x 32 fp16] = 8KB (64B rows, SW64) at +16384. Stage = 24KB, 4 stages.
#define STG1 24576
static constexpr int SMEM1 = 4 * STG1;       // 96KB/CTA -> 2 CTAs/SM
// gemm2 stage: as before, 32KB x 3 stages
#define STG2 32768
static constexpr int SMEM2 = 3 * STG2;

// ---- gemm1 chunk: fp16 2-split (Ah*B + Al*B), 128x128x32, 8 warps, warp tile 32x64 ----
__device__ __forceinline__ void compute_chunk1(uint32_t base, float acc[2][8][4],
                                               int lane, int wm, int wn)
{
    const uint32_t saA = base, saB = base + 16384;
    #pragma unroll
    for (int ks = 0; ks < 2; ks++) {
        uint32_t ah[2][4], al[2][4];
        const uint32_t kb = ks * 32 + (lane >> 4) * 16;
        #pragma unroll
        for (int mf = 0; mf < 2; mf++) {
            uint32_t rb = (wm * 32 + mf * 16 + (lane & 15)) * 128;
            LDMX4(ah[mf], saA + SWZ(rb + kb));
            LDMX4(al[mf], saA + SWZ(rb + 64 + kb));
        }
        const uint32_t kbB = ks * 32 + ((lane >> 3) & 1) * 16;
        #pragma unroll
        for (int np = 0; np < 4; np++) {
            uint32_t rb = (wn * 64 + np * 16 + ((lane >> 4) << 3) + (lane & 7)) * 64;
            uint32_t bh[4];
            LDMX4(bh, saB + SWZ64(rb + kbB));
            MMAF16(acc[0][2 * np],     ah[0], bh[0], bh[1]);
            MMAF16(acc[0][2 * np + 1], ah[0], bh[2], bh[3]);
            MMAF16(acc[1][2 * np],     ah[1], bh[0], bh[1]);
            MMAF16(acc[1][2 * np + 1], ah[1], bh[2], bh[3]);
            MMAF16(acc[0][2 * np],     al[0], bh[0], bh[1]);
            MMAF16(acc[0][2 * np + 1], al[0], bh[2], bh[3]);
            MMAF16(acc[1][2 * np],     al[1], bh[0], bh[1]);
            MMAF16(acc[1][2 * np + 1], al[1], bh[2], bh[3]);
        }
    }
}

__device__ __forceinline__ void g1_load(uint32_t base, int tid, int row0, int bn0, int k0) {
    #pragma unroll
    for (int j = 0; j < 4; j++) {          // A: 1024 cp16
        int i = tid + j * 256;
        int r = i >> 3, c = i & 7;
        int hi = (c < 4), cc = c & 3;
        uint32_t dst = SWZ(r * 128 + (hi ? 0 : 64) + cc * 16);
        const __half* src = (hi ? g_xh16 : g_xl16) + (size_t)(row0 + r) * CINK + k0 + cc * 8;
        CP16(base + dst, src);
    }
    #pragma unroll
    for (int j = 0; j < 2; j++) {          // B: 512 cp16
        int i = tid + j * 256;
        int r = i >> 2, c = i & 3;
        uint32_t dst = SWZ64(r * 64 + c * 16);
        CP16(base + 16384 + dst, g_W16 + (size_t)(bn0 + r) * CINK + k0 + c * 8);
    }
}

// ---- gemm2 chunk: bf16 3-split (unchanged, proven) ----
__device__ __forceinline__ void compute_chunk2(uint32_t base, float acc[2][8][4],
                                               int lane, int wm, int wn)
{
    const uint32_t saA = base, saB = base + 16384;
    #pragma unroll
    for (int ks = 0; ks < 2; ks++) {
        uint32_t ah[2][4], al[2][4];
        const uint32_t kb = ks * 32 + (lane >> 4) * 16;
        #pragma unroll
        for (int mf = 0; mf < 2; mf++) {
            uint32_t rb = (wm * 32 + mf * 16 + (lane & 15)) * 128;
            LDMX4(ah[mf], saA + SWZ(rb + kb));
            LDMX4(al[mf], saA + SWZ(rb + 64 + kb));
        }
        const uint32_t kbB = ks * 32 + ((lane >> 3) & 1) * 16;
        #pragma unroll
        for (int np = 0; np < 4; np++) {
            uint32_t rb = (wn * 64 + np * 16 + ((lane >> 4) << 3) + (lane & 7)) * 128;
            uint32_t bh[4], bl[4];
            LDMX4(bh, saB + SWZ(rb + kbB));
            LDMX4(bl, saB + SWZ(rb + 64 + kbB));
            MMAB16(acc[0][2 * np],     ah[0], bh[0], bh[1]);
            MMAB16(acc[0][2 * np + 1], ah[0], bh[2], bh[3]);
            MMAB16(acc[1][2 * np],     ah[1], bh[0], bh[1]);
            MMAB16(acc[1][2 * np + 1], ah[1], bh[2], bh[3]);
            MMAB16(acc[0][2 * np],     ah[0], bl[0], bl[1]);
            MMAB16(acc[0][2 * np + 1], ah[0], bl[2], bl[3]);
            MMAB16(acc[1][2 * np],     ah[1], bl[0], bl[1]);
            MMAB16(acc[1][2 * np + 1], ah[1], bl[2], bl[3]);
            MMAB16(acc[0][2 * np],     al[0], bh[0], bh[1]);
            MMAB16(acc[0][2 * np + 1], al[0], bh[2], bh[3]);
            MMAB16(acc[1][2 * np],     al[1], bh[0], bh[1]);
            MMAB16(acc[1][2 * np + 1], al[1], bh[2], bh[3]);
        }
    }
}

__device__ __forceinline__ void g2_load(uint32_t base, int tid,
    size_t aoff, size_t boff, int k0)
{
    #pragma unroll
    for (int j = 0; j < 4; j++) {
        int i = tid + j * 256;
        int r = i >> 3, c = i & 7;
        int hi = (c < 4), cc = c & 3;
        uint32_t dst = SWZ(r * 128 + (hi ? 0 : 64) + cc * 16);
        const __nv_bfloat16* asrc = (hi ? g_p_hi : g_p_lo) + aoff + (size_t)r * ETOT + k0 + cc * 8;
        const __nv_bfloat16* bsrc = (hi ? g_CBThi : g_CBTlo) + boff + (size_t)r * ENT + k0 + cc * 8;
        CP16(base + dst,         asrc);
        CP16(base + 16384 + dst, bsrc);
    }
}

// ---------------- prep kernels ----------------
__global__ void split_x16(const float* __restrict__ x) {
    size_t i = (size_t)blockIdx.x * 256 + threadIdx.x;
    float4 v = __ldg((const float4*)x + i);
    uint32_t h0, l0, h1, l1, h2, l2, h3, l3;
    split1h(v.x, h0, l0); split1h(v.y, h1, l1); split1h(v.z, h2, l2); split1h(v.w, h3, l3);
    *(uint2*)(g_xh16 + i * 4) = make_uint2(h0 | (h1 << 16), h2 | (h3 << 16));
    *(uint2*)(g_xl16 + i * 4) = make_uint2(l0 | (l1 << 16), l2 | (l3 << 16));
}
__global__ void split_w16(const float* __restrict__ Wp) {
    int i = blockIdx.x * 256 + threadIdx.x;
    if (i < ETOT * CINK) g_W16[i] = __float2half(__ldg(Wp + i));
}
__global__ void split_cbt(const float* __restrict__ cb) {
    int i = blockIdx.x * 256 + threadIdx.x;   // i = (g*DD + d)*ENT + e
    if (i < 2 * DD * ENT) {
        int e = i % ENT, d = (i / ENT) % DD, g = i / (ENT * DD);
        uint32_t h, l; split1(__ldg(cb + ((size_t)g * ENT + e) * DD + d), h, l);
        g_CBThi[i] = __ushort_as_bfloat16((unsigned short)h);
        g_CBTlo[i] = __ushort_as_bfloat16((unsigned short)l);
    }
}

// ---------------- kernel 1: logits GEMM + fused exp(logit+bias+gumbel) ----------------
__global__ __launch_bounds__(256, 2) void gemm1(
    const float* __restrict__ bp, const float* __restrict__ gum)
{
    extern __shared__ char smem[];
    const uint32_t sb = smem_u32(smem);
    const int tid = threadIdx.x, lane = tid & 31, wid = tid >> 5;
    const int wm = wid & 3, wn = wid >> 2;
    const int row0 = blockIdx.x * 128, bn0 = blockIdx.y * 128;

    float acc[2][8][4];
    #pragma unroll
    for (int i = 0; i < 2; i++)
        #pragma unroll
        for (int j = 0; j < 8; j++)
            #pragma unroll
            for (int q = 0; q < 4; q++) acc[i][j][q] = 0.f;

    g1_load(sb,        tid, row0, bn0, 0);  CP_COMMIT();
    g1_load(sb + STG1, tid, row0, bn0, 32); CP_COMMIT();

    for (int kc = 0; kc < 16; kc++) {
        if (kc + 2 < 16)
            g1_load(sb + ((kc + 2) & 3) * STG1, tid, row0, bn0, (kc + 2) * 32);
        CP_COMMIT();                  // uniform group count
        CP_WAIT2();
        __syncthreads();              // single barrier per chunk (4-stage ring)
        compute_chunk1(sb + (kc & 3) * STG1, acc, lane, wm, wn);
    }

    // epilogue: p = exp(logit + bias + gumbel), store bf16 hi/lo
    #pragma unroll
    for (int mf = 0; mf < 2; mf++) {
        #pragma unroll
        for (int h = 0; h < 2; h++) {
            const int r = wm * 32 + mf * 16 + (lane >> 2) + h * 8;
            const size_t grow = row0 + r;
            #pragma unroll
            for (int nf = 0; nf < 8; nf++) {
                const int e = bn0 + wn * 64 + nf * 8 + (lane & 3) * 2;
                float2 gv = *(const float2*)(gum + grow * ETOT + e);
                float2 bv = *(const float2*)(bp + e);
                float p0 = __expf(acc[mf][nf][h * 2 + 0] + bv.x + gv.x);
                float p1 = __expf(acc[mf][nf][h * 2 + 1] + bv.y + gv.y);
                uint32_t h0, l0, h1, l1;
                split1(p0, h0, l0); split1(p1, h1, l1);
                *(uint32_t*)(g_p_hi + grow * ETOT + e) = h0 | (h1 << 16);
                *(uint32_t*)(g_p_lo + grow * ETOT + e) = l0 | (l1 << 16);
            }
        }
    }
}

// ---------------- Z kernel: deterministic per-row sum of p ----------------
__global__ __launch_bounds__(256) void zsum() {
    const int r = blockIdx.x * 8 + (threadIdx.x >> 5);
    const int lane = threadIdx.x & 31;
    const uint32_t* ph = (const uint32_t*)(g_p_hi + (size_t)r * ETOT);
    const uint32_t* pl = (const uint32_t*)(g_p_lo + (size_t)r * ETOT);
    float s = 0.f;
    #pragma unroll
    for (int i = lane; i < ETOT / 2; i += 32) {
        uint32_t hw = __ldg(ph + i), lw = __ldg(pl + i);
        float2 hf = __bfloat1622float2(*(const __nv_bfloat162*)&hw);
        float2 lf = __bfloat1622float2(*(const __nv_bfloat162*)&lw);
        s += (hf.x + lf.x) + (hf.y + lf.y);
    }
    #pragma unroll
    for (int o = 16; o; o >>= 1) s += __shfl_xor_sync(0xFFFFFFFFu, s, o);
    if (lane == 0) g_Z[r] = s;
}

// ---------------- kernel 2: block-diagonal codebook GEMM, /Z epilogue ----------------
__global__ __launch_bounds__(256, 2) void gemm2(float* __restrict__ out)
{
    extern __shared__ char smem[];
    const uint32_t sb = smem_u32(smem);
    const int tid = threadIdx.x, lane = tid & 31, wid = tid >> 5;
    const int wm = wid & 3, wn = wid >> 2;
    const int row0 = blockIdx.x * 128;
    const int g = blockIdx.y >> 1;
    const int d0 = (blockIdx.y & 1) * 128;
    const int oc0 = blockIdx.y * 128;

    float acc[2][8][4];
    #pragma unroll
    for (int i = 0; i < 2; i++)
        #pragma unroll
        for (int j = 0; j < 8; j++)
            #pragma unroll
            for (int q = 0; q < 4; q++) acc[i][j][q] = 0.f;

    const size_t aoff = (size_t)row0 * ETOT + (size_t)g * ENT;
    const size_t boff = (size_t)(g * DD + d0) * ENT;

    g2_load(sb,        tid, aoff, boff, 0);  CP_COMMIT();
    g2_load(sb + STG2, tid, aoff, boff, 32); CP_COMMIT();

    for (int kc = 0; kc < 10; kc++) {
        if (kc + 2 < 10)
            g2_load(sb + ((kc + 2) % 3) * STG2, tid, aoff, boff, (kc + 2) * 32);
        CP_COMMIT();
        CP_WAIT2();
        __syncthreads();
        compute_chunk2(sb + (kc % 3) * STG2, acc, lane, wm, wn);
        __syncthreads();
    }

    // epilogue: out = acc / Z
    #pragma unroll
    for (int mf = 0; mf < 2; mf++) {
        #pragma unroll
        for (int h = 0; h < 2; h++) {
            const int r = wm * 32 + mf * 16 + (lane >> 2) + h * 8;
            const size_t grow = row0 + r;
            const float rz = 1.0f / g_Z[grow];
            #pragma unroll
            for (int nf = 0; nf < 8; nf++) {
                const int oc = oc0 + wn * 64 + nf * 8 + (lane & 3) * 2;
                float2 o;
                o.x = acc[mf][nf][h * 2 + 0] * rz;
                o.y = acc[mf][nf][h * 2 + 1] * rz;
                *(float2*)(out + grow * 512 + oc) = o;
            }
        }
    }
}

// ---------------- launch ----------------
extern "C" void kernel_launch(void* const* d_in, const int* in_sizes, int n_in,
                              void* d_out, int out_size) {
    const float* x  = (const float*)d_in[0];
    const float* Wp = (const float*)d_in[1];
    const float* bp = (const float*)d_in[2];
    const float* cb = (const float*)d_in[3];
    const float* gu = (const float*)d_in[4];
    float* out = (float*)d_out;

    cudaFuncSetAttribute(gemm1, cudaFuncAttributeMaxDynamicSharedMemorySize, SMEM1);
    cudaFuncSetAttribute(gemm2, cudaFuncAttributeMaxDynamicSharedMemorySize, SMEM2);

    split_x16<<<(RTOT * CINK / 4) / 256, 256>>>(x);
    split_w16<<<(ETOT * CINK + 255) / 256, 256>>>(Wp);
    split_cbt<<<(2 * DD * ENT + 255) / 256, 256>>>(cb);
    gemm1<<<dim3(RTOT / 128, ETOT / 128), 256, SMEM1>>>(bp, gu);
    zsum<<<RTOT / 8, 256>>>();
    gemm2<<<dim3(RTOT / 128, 4), 256, SMEM2>>>(out);
}

// round 11
// speedup vs baseline: 1.6677x; 1.3154x over previous
#include <cuda_runtime.h>
#include <cuda_bf16.h>
#include <cuda_fp16.h>
#include <cstdint>
#include <cstddef>

#define RTOT 32768
#define CINK 512
#define ETOT 640
#define ENT  320
#define DD   256

// ---------------- device scratch ----------------
__device__ __half        g_x16[(size_t)RTOT * CINK];     // x single fp16
__device__ __half        g_W16[ETOT * CINK];             // Wp single fp16
__device__ __nv_bfloat16 g_p_hi[(size_t)RTOT * ETOT];    // unnormalized exp, bf16 pair
__device__ __nv_bfloat16 g_p_lo[(size_t)RTOT * ETOT];
__device__ __half        g_pnh[(size_t)RTOT * ETOT];     // normalized p, fp16 pair
__device__ __half        g_pnl[(size_t)RTOT * ETOT];
__device__ __half        g_cbt16[2 * DD * ENT];          // codebook^T single fp16

// ---------------- helpers ----------------
__device__ __forceinline__ uint32_t smem_u32(const void* p) {
    uint32_t a;
    asm("{ .reg .u64 t; cvta.to.shared.u64 t, %1; cvt.u32.u64 %0, t; }" : "=r"(a) : "l"(p));
    return a;
}
#define SWZ(o)   ((uint32_t)(o) ^ ((((uint32_t)(o)) >> 3) & 0x70))
#define SWZ64(o) ((uint32_t)(o) ^ ((((uint32_t)(o)) >> 3) & 0x30))

#define LDMX4(d, addr) \
    asm volatile("ldmatrix.sync.aligned.m8n8.x4.shared.b16 {%0,%1,%2,%3}, [%4];" \
                 : "=r"((d)[0]), "=r"((d)[1]), "=r"((d)[2]), "=r"((d)[3]) : "r"(addr))

#define MMAF16(c, a, b0, b1) \
    asm volatile("mma.sync.aligned.m16n8k16.row.col.f32.f16.f16.f32 " \
                 "{%0,%1,%2,%3},{%4,%5,%6,%7},{%8,%9},{%0,%1,%2,%3};" \
                 : "+f"((c)[0]), "+f"((c)[1]), "+f"((c)[2]), "+f"((c)[3]) \
                 : "r"((a)[0]), "r"((a)[1]), "r"((a)[2]), "r"((a)[3]), "r"(b0), "r"(b1))

#define CP16(saddr, gptr) \
    asm volatile("cp.async.cg.shared.global [%0], [%1], 16;" :: "r"(saddr), "l"(gptr) : "memory")
#define CP_COMMIT() asm volatile("cp.async.commit_group;" ::: "memory")
#define CP_WAIT2()  asm volatile("cp.async.wait_group 2;" ::: "memory")

__device__ __forceinline__ void split1(float v, uint32_t& h, uint32_t& l) {
    __nv_bfloat16 hb = __float2bfloat16(v);
    h = __bfloat16_as_ushort(hb);
    l = __bfloat16_as_ushort(__float2bfloat16(v - __bfloat162float(hb)));
}
__device__ __forceinline__ void split1h(float v, uint32_t& h, uint32_t& l) {
    __half hb = __float2half(v);
    h = __half_as_ushort(hb);
    l = __half_as_ushort(__float2half(v - __half2float(hb)));
}

// gemm1 stage: A [128r x 32 fp16] 8KB (64B rows, SW64) @0; B same @8192. 16KB x 4 stages.
#define STG1 16384
static constexpr int SMEM1 = 4 * STG1;     // 64KB/CTA
// gemm2 stage: A [128r x (32 hi|32 lo) fp16] 16KB (128B rows, SW128) @0; B 8KB SW64 @16384.
#define STG2 24576
static constexpr int SMEM2 = 4 * STG2;     // 96KB/CTA

// ---- gemm1 chunk: single fp16 A*B, 128x128x32, 8 warps, warp tile 32x64 ----
__device__ __forceinline__ void chunk1(uint32_t base, float acc[2][8][4], int lane, int wm, int wn)
{
    const uint32_t saA = base, saB = base + 8192;
    #pragma unroll
    for (int ks = 0; ks < 2; ks++) {
        uint32_t ah[2][4];
        const uint32_t kb = ks * 32 + (lane >> 4) * 16;
        #pragma unroll
        for (int mf = 0; mf < 2; mf++) {
            uint32_t rb = (wm * 32 + mf * 16 + (lane & 15)) * 64;
            LDMX4(ah[mf], saA + SWZ64(rb + kb));
        }
        const uint32_t kbB = ks * 32 + ((lane >> 3) & 1) * 16;
        #pragma unroll
        for (int np = 0; np < 4; np++) {
            uint32_t rb = (wn * 64 + np * 16 + ((lane >> 4) << 3) + (lane & 7)) * 64;
            uint32_t bh[4];
            LDMX4(bh, saB + SWZ64(rb + kbB));
            MMAF16(acc[0][2 * np],     ah[0], bh[0], bh[1]);
            MMAF16(acc[0][2 * np + 1], ah[0], bh[2], bh[3]);
            MMAF16(acc[1][2 * np],     ah[1], bh[0], bh[1]);
            MMAF16(acc[1][2 * np + 1], ah[1], bh[2], bh[3]);
        }
    }
}

// ---- gemm2 chunk: fp16 2-split (Ah+Al)*B, A packed hi|lo SW128, B SW64 single ----
__device__ __forceinline__ void chunk2(uint32_t base, float acc[2][8][4], int lane, int wm, int wn)
{
    const uint32_t saA = base, saB = base + 16384;
    #pragma unroll
    for (int ks = 0; ks < 2; ks++) {
        uint32_t ah[2][4], al[2][4];
        const uint32_t kb = ks * 32 + (lane >> 4) * 16;
        #pragma unroll
        for (int mf = 0; mf < 2; mf++) {
            uint32_t rb = (wm * 32 + mf * 16 + (lane & 15)) * 128;
            LDMX4(ah[mf], saA + SWZ(rb + kb));
            LDMX4(al[mf], saA + SWZ(rb + 64 + kb));
        }
        const uint32_t kbB = ks * 32 + ((lane >> 3) & 1) * 16;
        #pragma unroll
        for (int np = 0; np < 4; np++) {
            uint32_t rb = (wn * 64 + np * 16 + ((lane >> 4) << 3) + (lane & 7)) * 64;
            uint32_t bh[4];
            LDMX4(bh, saB + SWZ64(rb + kbB));
            MMAF16(acc[0][2 * np],     ah[0], bh[0], bh[1]);
            MMAF16(acc[0][2 * np + 1], ah[0], bh[2], bh[3]);
            MMAF16(acc[1][2 * np],     ah[1], bh[0], bh[1]);
            MMAF16(acc[1][2 * np + 1], ah[1], bh[2], bh[3]);
            MMAF16(acc[0][2 * np],     al[0], bh[0], bh[1]);
            MMAF16(acc[0][2 * np + 1], al[0], bh[2], bh[3]);
            MMAF16(acc[1][2 * np],     al[1], bh[0], bh[1]);
            MMAF16(acc[1][2 * np + 1], al[1], bh[2], bh[3]);
        }
    }
}

// ---------------- prep kernels ----------------
__global__ void split_x16(const float* __restrict__ x) {
    size_t i = (size_t)blockIdx.x * 256 + threadIdx.x;
    float4 v = __ldg((const float4*)x + i);
    uint32_t a = __half_as_ushort(__float2half(v.x)) | ((uint32_t)__half_as_ushort(__float2half(v.y)) << 16);
    uint32_t b = __half_as_ushort(__float2half(v.z)) | ((uint32_t)__half_as_ushort(__float2half(v.w)) << 16);
    *(uint2*)(g_x16 + i * 4) = make_uint2(a, b);
}
__global__ void split_w16(const float* __restrict__ Wp) {
    int i = blockIdx.x * 256 + threadIdx.x;
    if (i < ETOT * CINK) g_W16[i] = __float2half(__ldg(Wp + i));
}
__global__ void split_cbt16(const float* __restrict__ cb) {
    int i = blockIdx.x * 256 + threadIdx.x;   // i = (g*DD + d)*ENT + e
    if (i < 2 * DD * ENT) {
        int e = i % ENT, d = (i / ENT) % DD, g = i / (ENT * DD);
        g_cbt16[i] = __float2half(__ldg(cb + ((size_t)g * ENT + e) * DD + d));
    }
}

// ---------------- kernel 1: logits GEMM + fused exp(logit+bias+gumbel) ----------------
__device__ __forceinline__ void g1_load(uint32_t base, int tid, int row0, int bn0, int k0) {
    #pragma unroll
    for (int j = 0; j < 2; j++) {
        int i = tid + j * 256;
        int r = i >> 2, c = i & 3;
        uint32_t dst = SWZ64(r * 64 + c * 16);
        CP16(base + dst,        g_x16 + (size_t)(row0 + r) * CINK + k0 + c * 8);
        CP16(base + 8192 + dst, g_W16 + (size_t)(bn0 + r) * CINK + k0 + c * 8);
    }
}

__global__ __launch_bounds__(256, 2) void gemm1(
    const float* __restrict__ bp, const float* __restrict__ gum)
{
    extern __shared__ char smem[];
    const uint32_t sb = smem_u32(smem);
    const int tid = threadIdx.x, lane = tid & 31, wid = tid >> 5;
    const int wm = wid & 3, wn = wid >> 2;
    const int row0 = blockIdx.x * 128, bn0 = blockIdx.y * 128;

    float acc[2][8][4];
    #pragma unroll
    for (int i = 0; i < 2; i++)
        #pragma unroll
        for (int j = 0; j < 8; j++)
            #pragma unroll
            for (int q = 0; q < 4; q++) acc[i][j][q] = 0.f;

    g1_load(sb,        tid, row0, bn0, 0);  CP_COMMIT();
    g1_load(sb + STG1, tid, row0, bn0, 32); CP_COMMIT();

    for (int kc = 0; kc < 16; kc++) {
        if (kc + 2 < 16)
            g1_load(sb + ((kc + 2) & 3) * STG1, tid, row0, bn0, (kc + 2) * 32);
        CP_COMMIT();
        CP_WAIT2();
        __syncthreads();
        chunk1(sb + (kc & 3) * STG1, acc, lane, wm, wn);
    }

    // epilogue: p = exp(logit + bias + gumbel), store bf16 hi/lo (full range)
    #pragma unroll
    for (int mf = 0; mf < 2; mf++) {
        #pragma unroll
        for (int h = 0; h < 2; h++) {
            const int r = wm * 32 + mf * 16 + (lane >> 2) + h * 8;
            const size_t grow = row0 + r;
            #pragma unroll
            for (int nf = 0; nf < 8; nf++) {
                const int e = bn0 + wn * 64 + nf * 8 + (lane & 3) * 2;
                float2 gv = *(const float2*)(gum + grow * ETOT + e);
                float2 bv = *(const float2*)(bp + e);
                float p0 = __expf(acc[mf][nf][h * 2 + 0] + bv.x + gv.x);
                float p1 = __expf(acc[mf][nf][h * 2 + 1] + bv.y + gv.y);
                uint32_t h0, l0, h1, l1;
                split1(p0, h0, l0); split1(p1, h1, l1);
                *(uint32_t*)(g_p_hi + grow * ETOT + e) = h0 | (h1 << 16);
                *(uint32_t*)(g_p_lo + grow * ETOT + e) = l0 | (l1 << 16);
            }
        }
    }
}

// ---- zsum_norm: per-row Z, then write normalized p as fp16 hi/lo pair ----
__global__ __launch_bounds__(256) void zsum_norm() {
    const int r = blockIdx.x * 8 + (threadIdx.x >> 5);
    const int lane = threadIdx.x & 31;
    const uint32_t* ph = (const uint32_t*)(g_p_hi + (size_t)r * ETOT);
    const uint32_t* pl = (const uint32_t*)(g_p_lo + (size_t)r * ETOT);
    float pv[20];
    float s = 0.f;
    #pragma unroll
    for (int j = 0; j < 10; j++) {
        int i = lane + j * 32;
        uint32_t hw = __ldg(ph + i), lw = __ldg(pl + i);
        float2 hf = __bfloat1622float2(*(const __nv_bfloat162*)&hw);
        float2 lf = __bfloat1622float2(*(const __nv_bfloat162*)&lw);
        pv[2 * j]     = hf.x + lf.x;
        pv[2 * j + 1] = hf.y + lf.y;
        s += pv[2 * j] + pv[2 * j + 1];
    }
    #pragma unroll
    for (int o = 16; o; o >>= 1) s += __shfl_xor_sync(0xFFFFFFFFu, s, o);
    const float rz = 1.0f / s;        // all lanes hold identical s (butterfly)
    uint32_t* onh = (uint32_t*)(g_pnh + (size_t)r * ETOT);
    uint32_t* onl = (uint32_t*)(g_pnl + (size_t)r * ETOT);
    #pragma unroll
    for (int j = 0; j < 10; j++) {
        int i = lane + j * 32;
        uint32_t h0, l0, h1, l1;
        split1h(pv[2 * j] * rz, h0, l0);
        split1h(pv[2 * j + 1] * rz, h1, l1);
        onh[i] = h0 | (h1 << 16);
        onl[i] = l0 | (l1 << 16);
    }
}

// ---------------- kernel 2: block-diagonal codebook GEMM (pre-normalized A) ----------------
__device__ __forceinline__ void g2_load(uint32_t base, int tid, size_t aoff, size_t boff, int k0) {
    #pragma unroll
    for (int j = 0; j < 4; j++) {              // A: packed hi|lo, 128B rows
        int i = tid + j * 256;
        int r = i >> 3, c = i & 7;
        int hi = (c < 4), cc = c & 3;
        uint32_t dst = SWZ(r * 128 + (hi ? 0 : 64) + cc * 16);
        const __half* src = (hi ? g_pnh : g_pnl) + aoff + (size_t)r * ETOT + k0 + cc * 8;
        CP16(base + dst, src);
    }
    #pragma unroll
    for (int j = 0; j < 2; j++) {              // B: single, 64B rows
        int i = tid + j * 256;
        int r = i >> 2, c = i & 3;
        uint32_t dst = SWZ64(r * 64 + c * 16);
        CP16(base + 16384 + dst, g_cbt16 + boff + (size_t)r * ENT + k0 + c * 8);
    }
}

__global__ __launch_bounds__(256, 2) void gemm2(float* __restrict__ out)
{
    extern __shared__ char smem[];
    const uint32_t sb = smem_u32(smem);
    const int tid = threadIdx.x, lane = tid & 31, wid = tid >> 5;
    const int wm = wid & 3, wn = wid >> 2;
    const int row0 = blockIdx.x * 128;
    const int g = blockIdx.y >> 1;
    const int d0 = (blockIdx.y & 1) * 128;
    const int oc0 = blockIdx.y * 128;

    float acc[2][8][4];
    #pragma unroll
    for (int i = 0; i < 2; i++)
        #pragma unroll
        for (int j = 0; j < 8; j++)
            #pragma unroll
            for (int q = 0; q < 4; q++) acc[i][j][q] = 0.f;

    const size_t aoff = (size_t)row0 * ETOT + (size_t)g * ENT;
    const size_t boff = (size_t)(g * DD + d0) * ENT;

    g2_load(sb,        tid, aoff, boff, 0);  CP_COMMIT();
    g2_load(sb + STG2, tid, aoff, boff, 32); CP_COMMIT();

    for (int kc = 0; kc < 10; kc++) {
        if (kc + 2 < 10)
            g2_load(sb + ((kc + 2) & 3) * STG2, tid, aoff, boff, (kc + 2) * 32);
        CP_COMMIT();
        CP_WAIT2();
        __syncthreads();
        chunk2(sb + (kc & 3) * STG2, acc, lane, wm, wn);
    }

    // epilogue: direct store (already normalized)
    #pragma unroll
    for (int mf = 0; mf < 2; mf++) {
        #pragma unroll
        for (int h = 0; h < 2; h++) {
            const int r = wm * 32 + mf * 16 + (lane >> 2) + h * 8;
            const size_t grow = row0 + r;
            #pragma unroll
            for (int nf = 0; nf < 8; nf++) {
                const int oc = oc0 + wn * 64 + nf * 8 + (lane & 3) * 2;
                float2 o;
                o.x = acc[mf][nf][h * 2 + 0];
                o.y = acc[mf][nf][h * 2 + 1];
                *(float2*)(out + grow * 512 + oc) = o;
            }
        }
    }
}

// ---------------- launch ----------------
extern "C" void kernel_launch(void* const* d_in, const int* in_sizes, int n_in,
                              void* d_out, int out_size) {
    const float* x  = (const float*)d_in[0];
    const float* Wp = (const float*)d_in[1];
    const float* bp = (const float*)d_in[2];
    const float* cb = (const float*)d_in[3];
    const float* gu = (const float*)d_in[4];
    float* out = (float*)d_out;

    cudaFuncSetAttribute(gemm1, cudaFuncAttributeMaxDynamicSharedMemorySize, SMEM1);
    cudaFuncSetAttribute(gemm2, cudaFuncAttributeMaxDynamicSharedMemorySize, SMEM2);

    split_x16<<<(RTOT * CINK / 4) / 256, 256>>>(x);
    split_w16<<<(ETOT * CINK + 255) / 256, 256>>>(Wp);
    split_cbt16<<<(2 * DD * ENT + 255) / 256, 256>>>(cb);
    gemm1<<<dim3(RTOT / 128, ETOT / 128), 256, SMEM1>>>(bp, gu);
    zsum_norm<<<RTOT / 8, 256>>>();
    gemm2<<<dim3(RTOT / 128, 4), 256, SMEM2>>>(out);
}

// round 12
// speedup vs baseline: 2.1489x; 1.2885x over previous
#include <cuda_runtime.h>
#include <cuda_bf16.h>
#include <cuda_fp16.h>
#include <cstdint>
#include <cstddef>

#define RTOT 32768
#define CINK 512
#define ETOT 640
#define ENT  320
#define DD   256

// ---------------- device scratch ----------------
__device__ __half g_x16[(size_t)RTOT * CINK];    // x single fp16
__device__ __half g_W16[ETOT * CINK];            // Wp single fp16
__device__ float  g_p[(size_t)RTOT * ETOT];      // unnormalized exp, fp32
__device__ __half g_pn16[(size_t)RTOT * ETOT];   // normalized p, single fp16
__device__ __half g_cbt16[2 * DD * ENT];         // codebook^T single fp16

// ---------------- helpers ----------------
__device__ __forceinline__ uint32_t smem_u32(const void* p) {
    uint32_t a;
    asm("{ .reg .u64 t; cvta.to.shared.u64 t, %1; cvt.u32.u64 %0, t; }" : "=r"(a) : "l"(p));
    return a;
}
#define SWZ(o)   ((uint32_t)(o) ^ ((((uint32_t)(o)) >> 3) & 0x70))
#define SWZ64(o) ((uint32_t)(o) ^ ((((uint32_t)(o)) >> 3) & 0x30))

#define LDMX4(d, addr) \
    asm volatile("ldmatrix.sync.aligned.m8n8.x4.shared.b16 {%0,%1,%2,%3}, [%4];" \
                 : "=r"((d)[0]), "=r"((d)[1]), "=r"((d)[2]), "=r"((d)[3]) : "r"(addr))

#define MMAF16(c, a, b0, b1) \
    asm volatile("mma.sync.aligned.m16n8k16.row.col.f32.f16.f16.f32 " \
                 "{%0,%1,%2,%3},{%4,%5,%6,%7},{%8,%9},{%0,%1,%2,%3};" \
                 : "+f"((c)[0]), "+f"((c)[1]), "+f"((c)[2]), "+f"((c)[3]) \
                 : "r"((a)[0]), "r"((a)[1]), "r"((a)[2]), "r"((a)[3]), "r"(b0), "r"(b1))

#define CP16(saddr, gptr) \
    asm volatile("cp.async.cg.shared.global [%0], [%1], 16;" :: "r"(saddr), "l"(gptr) : "memory")
#define CP_COMMIT() asm volatile("cp.async.commit_group;" ::: "memory")
#define CP_WAIT1()  asm volatile("cp.async.wait_group 1;" ::: "memory")

// gemm1 stage: A [128r x 64 fp16] 16KB (128B rows, SW128) @0; B same @16384. 32KB x 3.
#define STG1 32768
static constexpr int SMEM1 = 3 * STG1;     // 96KB/CTA -> 2 CTAs/SM
// gemm2 stage: A [128r x 32 fp16] 8KB (64B rows, SW64) @0; B same @8192. 16KB x 3.
#define STG2 16384
static constexpr int SMEM2 = 3 * STG2;     // 48KB/CTA

// ---- gemm1 chunk: single fp16, 128x128x64, 8 warps, warp tile 32x64 ----
__device__ __forceinline__ void chunk1(uint32_t base, float acc[2][8][4], int lane, int wm, int wn)
{
    const uint32_t saA = base, saB = base + 16384;
    #pragma unroll
    for (int ks = 0; ks < 4; ks++) {
        uint32_t ah[2][4];
        const uint32_t kb = ks * 32 + (lane >> 4) * 16;
        #pragma unroll
        for (int mf = 0; mf < 2; mf++) {
            uint32_t rb = (wm * 32 + mf * 16 + (lane & 15)) * 128;
            LDMX4(ah[mf], saA + SWZ(rb + kb));
        }
        const uint32_t kbB = ks * 32 + ((lane >> 3) & 1) * 16;
        #pragma unroll
        for (int np = 0; np < 4; np++) {
            uint32_t rb = (wn * 64 + np * 16 + ((lane >> 4) << 3) + (lane & 7)) * 128;
            uint32_t bh[4];
            LDMX4(bh, saB + SWZ(rb + kbB));
            MMAF16(acc[0][2 * np],     ah[0], bh[0], bh[1]);
            MMAF16(acc[0][2 * np + 1], ah[0], bh[2], bh[3]);
            MMAF16(acc[1][2 * np],     ah[1], bh[0], bh[1]);
            MMAF16(acc[1][2 * np + 1], ah[1], bh[2], bh[3]);
        }
    }
}

// ---- gemm2 chunk: single fp16, 128x128x32, 64B rows SW64 ----
__device__ __forceinline__ void chunk2(uint32_t base, float acc[2][8][4], int lane, int wm, int wn)
{
    const uint32_t saA = base, saB = base + 8192;
    #pragma unroll
    for (int ks = 0; ks < 2; ks++) {
        uint32_t ah[2][4];
        const uint32_t kb = ks * 32 + (lane >> 4) * 16;
        #pragma unroll
        for (int mf = 0; mf < 2; mf++) {
            uint32_t rb = (wm * 32 + mf * 16 + (lane & 15)) * 64;
            LDMX4(ah[mf], saA + SWZ64(rb + kb));
        }
        const uint32_t kbB = ks * 32 + ((lane >> 3) & 1) * 16;
        #pragma unroll
        for (int np = 0; np < 4; np++) {
            uint32_t rb = (wn * 64 + np * 16 + ((lane >> 4) << 3) + (lane & 7)) * 64;
            uint32_t bh[4];
            LDMX4(bh, saB + SWZ64(rb + kbB));
            MMAF16(acc[0][2 * np],     ah[0], bh[0], bh[1]);
            MMAF16(acc[0][2 * np + 1], ah[0], bh[2], bh[3]);
            MMAF16(acc[1][2 * np],     ah[1], bh[0], bh[1]);
            MMAF16(acc[1][2 * np + 1], ah[1], bh[2], bh[3]);
        }
    }
}

// ---------------- prep kernels ----------------
__global__ void split_x16(const float* __restrict__ x) {
    size_t i = (size_t)blockIdx.x * 256 + threadIdx.x;
    float4 v = __ldg((const float4*)x + i);
    uint32_t a = __half_as_ushort(__float2half(v.x)) | ((uint32_t)__half_as_ushort(__float2half(v.y)) << 16);
    uint32_t b = __half_as_ushort(__float2half(v.z)) | ((uint32_t)__half_as_ushort(__float2half(v.w)) << 16);
    *(uint2*)(g_x16 + i * 4) = make_uint2(a, b);
}
__global__ void split_w16(const float* __restrict__ Wp) {
    int i = blockIdx.x * 256 + threadIdx.x;
    if (i < ETOT * CINK) g_W16[i] = __float2half(__ldg(Wp + i));
}
__global__ void split_cbt16(const float* __restrict__ cb) {
    int i = blockIdx.x * 256 + threadIdx.x;   // i = (g*DD + d)*ENT + e
    if (i < 2 * DD * ENT) {
        int e = i % ENT, d = (i / ENT) % DD, g = i / (ENT * DD);
        g_cbt16[i] = __float2half(__ldg(cb + ((size_t)g * ENT + e) * DD + d));
    }
}

// ---------------- kernel 1: logits GEMM + fused exp(logit+bias+gumbel) ----------------
__device__ __forceinline__ void g1_load(uint32_t base, int tid, int row0, int bn0, int k0) {
    #pragma unroll
    for (int j = 0; j < 4; j++) {
        int i = tid + j * 256;
        int r = i >> 3, c = i & 7;
        uint32_t dst = SWZ(r * 128 + c * 16);
        CP16(base + dst,         g_x16 + (size_t)(row0 + r) * CINK + k0 + c * 8);
        CP16(base + 16384 + dst, g_W16 + (size_t)(bn0 + r) * CINK + k0 + c * 8);
    }
}

__global__ __launch_bounds__(256, 2) void gemm1(
    const float* __restrict__ bp, const float* __restrict__ gum)
{
    extern __shared__ char smem[];
    const uint32_t sb = smem_u32(smem);
    const int tid = threadIdx.x, lane = tid & 31, wid = tid >> 5;
    const int wm = wid & 3, wn = wid >> 2;
    const int row0 = blockIdx.x * 128, bn0 = blockIdx.y * 128;

    float acc[2][8][4];
    #pragma unroll
    for (int i = 0; i < 2; i++)
        #pragma unroll
        for (int j = 0; j < 8; j++)
            #pragma unroll
            for (int q = 0; q < 4; q++) acc[i][j][q] = 0.f;

    g1_load(sb,        tid, row0, bn0, 0);  CP_COMMIT();
    g1_load(sb + STG1, tid, row0, bn0, 64); CP_COMMIT();

    for (int kc = 0; kc < 8; kc++) {          // K chunks of 64
        CP_WAIT1();                           // group kc complete (newest may pend)
        __syncthreads();                      // all warps done with chunk kc-1
        if (kc + 2 < 8)
            g1_load(sb + ((kc + 2) % 3) * STG1, tid, row0, bn0, (kc + 2) * 64);
        CP_COMMIT();                          // uniform group count
        chunk1(sb + (kc % 3) * STG1, acc, lane, wm, wn);
    }

    // epilogue: p = exp(logit + bias + gumbel), store fp32
    #pragma unroll
    for (int mf = 0; mf < 2; mf++) {
        #pragma unroll
        for (int h = 0; h < 2; h++) {
            const int r = wm * 32 + mf * 16 + (lane >> 2) + h * 8;
            const size_t grow = row0 + r;
            #pragma unroll
            for (int nf = 0; nf < 8; nf++) {
                const int e = bn0 + wn * 64 + nf * 8 + (lane & 3) * 2;
                float2 gv = *(const float2*)(gum + grow * ETOT + e);
                float2 bv = *(const float2*)(bp + e);
                float2 pv;
                pv.x = __expf(acc[mf][nf][h * 2 + 0] + bv.x + gv.x);
                pv.y = __expf(acc[mf][nf][h * 2 + 1] + bv.y + gv.y);
                *(float2*)(g_p + grow * ETOT + e) = pv;
            }
        }
    }
}

// ---- zsum_norm: per-row Z from fp32 p, write normalized pn as single fp16 ----
__global__ __launch_bounds__(256) void zsum_norm() {
    const int r = blockIdx.x * 8 + (threadIdx.x >> 5);
    const int lane = threadIdx.x & 31;
    const float4* p4 = (const float4*)(g_p + (size_t)r * ETOT);
    float4 pv[5];
    float s = 0.f;
    #pragma unroll
    for (int j = 0; j < 5; j++) {
        pv[j] = __ldg(p4 + lane + j * 32);
        s += (pv[j].x + pv[j].y) + (pv[j].z + pv[j].w);
    }
    #pragma unroll
    for (int o = 16; o; o >>= 1) s += __shfl_xor_sync(0xFFFFFFFFu, s, o);
    const float rz = 1.0f / s;                 // identical in all lanes (butterfly)
    uint2* on = (uint2*)(g_pn16 + (size_t)r * ETOT);
    #pragma unroll
    for (int j = 0; j < 5; j++) {
        uint32_t a = __half_as_ushort(__float2half(pv[j].x * rz))
                   | ((uint32_t)__half_as_ushort(__float2half(pv[j].y * rz)) << 16);
        uint32_t b = __half_as_ushort(__float2half(pv[j].z * rz))
                   | ((uint32_t)__half_as_ushort(__float2half(pv[j].w * rz)) << 16);
        on[lane + j * 32] = make_uint2(a, b);
    }
}

// ---------------- kernel 2: block-diagonal codebook GEMM (normalized single-fp16 A) ----------------
__device__ __forceinline__ void g2_load(uint32_t base, int tid, size_t aoff, size_t boff, int k0) {
    #pragma unroll
    for (int j = 0; j < 2; j++) {
        int i = tid + j * 256;
        int r = i >> 2, c = i & 3;
        uint32_t dst = SWZ64(r * 64 + c * 16);
        CP16(base + dst,        g_pn16  + aoff + (size_t)r * ETOT + k0 + c * 8);
        CP16(base + 8192 + dst, g_cbt16 + boff + (size_t)r * ENT  + k0 + c * 8);
    }
}

__global__ __launch_bounds__(256, 2) void gemm2(float* __restrict__ out)
{
    extern __shared__ char smem[];
    const uint32_t sb = smem_u32(smem);
    const int tid = threadIdx.x, lane = tid & 31, wid = tid >> 5;
    const int wm = wid & 3, wn = wid >> 2;
    const int row0 = blockIdx.x * 128;
    const int g = blockIdx.y >> 1;
    const int d0 = (blockIdx.y & 1) * 128;
    const int oc0 = blockIdx.y * 128;

    float acc[2][8][4];
    #pragma unroll
    for (int i = 0; i < 2; i++)
        #pragma unroll
        for (int j = 0; j < 8; j++)
            #pragma unroll
            for (int q = 0; q < 4; q++) acc[i][j][q] = 0.f;

    const size_t aoff = (size_t)row0 * ETOT + (size_t)g * ENT;
    const size_t boff = (size_t)(g * DD + d0) * ENT;

    g2_load(sb,        tid, aoff, boff, 0);  CP_COMMIT();
    g2_load(sb + STG2, tid, aoff, boff, 32); CP_COMMIT();

    for (int kc = 0; kc < 10; kc++) {         // K chunks of 32 over ENT=320
        CP_WAIT1();
        __syncthreads();
        if (kc + 2 < 10)
            g2_load(sb + ((kc + 2) % 3) * STG2, tid, aoff, boff, (kc + 2) * 32);
        CP_COMMIT();
        chunk2(sb + (kc % 3) * STG2, acc, lane, wm, wn);
    }

    // epilogue: direct store (already normalized)
    #pragma unroll
    for (int mf = 0; mf < 2; mf++) {
        #pragma unroll
        for (int h = 0; h < 2; h++) {
            const int r = wm * 32 + mf * 16 + (lane >> 2) + h * 8;
            const size_t grow = row0 + r;
            #pragma unroll
            for (int nf = 0; nf < 8; nf++) {
                const int oc = oc0 + wn * 64 + nf * 8 + (lane & 3) * 2;
                float2 o;
                o.x = acc[mf][nf][h * 2 + 0];
                o.y = acc[mf][nf][h * 2 + 1];
                *(float2*)(out + grow * 512 + oc) = o;
            }
        }
    }
}

// ---------------- launch ----------------
extern "C" void kernel_launch(void* const* d_in, const int* in_sizes, int n_in,
                              void* d_out, int out_size) {
    const float* x  = (const float*)d_in[0];
    const float* Wp = (const float*)d_in[1];
    const float* bp = (const float*)d_in[2];
    const float* cb = (const float*)d_in[3];
    const float* gu = (const float*)d_in[4];
    float* out = (float*)d_out;

    cudaFuncSetAttribute(gemm1, cudaFuncAttributeMaxDynamicSharedMemorySize, SMEM1);
    cudaFuncSetAttribute(gemm2, cudaFuncAttributeMaxDynamicSharedMemorySize, SMEM2);

    split_x16<<<(RTOT * CINK / 4) / 256, 256>>>(x);
    split_w16<<<(ETOT * CINK + 255) / 256, 256>>>(Wp);
    split_cbt16<<<(2 * DD * ENT + 255) / 256, 256>>>(cb);
    gemm1<<<dim3(RTOT / 128, ETOT / 128), 256, SMEM1>>>(bp, gu);
    zsum_norm<<<RTOT / 8, 256>>>();
    gemm2<<<dim3(RTOT / 128, 4), 256, SMEM2>>>(out);
}